// round 5
// baseline (speedup 1.0000x reference)
#include <cuda_runtime.h>

#define N_NODES 100000
#define N_EDGES 1600000
#define DIM 64
#define SCAN_CHUNK 1024
#define NCH ((N_NODES + SCAN_CHUNK - 1) / SCAN_CHUNK)   // 98

// scratch (allocation-free: device globals)
__device__ float g_t[(size_t)N_NODES * DIM];   // h@W1 + b1
__device__ float g_sum[DIM];
__device__ float g_sq[DIM];
__device__ int   g_deg[N_NODES];
__device__ int   g_off[N_NODES];
__device__ int   g_cur[N_NODES];
__device__ int   g_csum[NCH];
__device__ unsigned g_es[N_EDGES];             // (attr<<28) | src

#define PACK2(d, lo, hi)  asm("mov.b64 %0, {%1, %2};" : "=l"(d) : "f"(lo), "f"(hi))
#define UNPACK2(lo, hi, s) asm("mov.b64 {%0, %1}, %2;" : "=f"(lo), "=f"(hi) : "l"(s))
#define FMA2(acc, a, b)   asm("fma.rn.f32x2 %0, %1, %2, %0;" : "+l"(acc) : "l"(a), "l"(b))

#define IN_STRIDE 132
// shared layout (floats): sW [0,4096) | sIn [4096, 4096+64*132) | s_emb [+256] / sAff [+128]
#define SM_W    0
#define SM_IN   4096
#define SM_AUX  (4096 + DIM * IN_STRIDE)
#define SMEM_FLOATS (SM_AUX + 256)

// ---------------------------------------------------------------------------
// K0: zero degree counters + BN accumulators
// ---------------------------------------------------------------------------
__global__ void zero_kernel() {
    int i = blockIdx.x * 256 + threadIdx.x;
    if (i < N_NODES) g_deg[i] = 0;
    if (i < DIM) { g_sum[i] = 0.0f; g_sq[i] = 0.0f; }
}

// ---------------------------------------------------------------------------
// K1: histogram of dst — 4 edges/thread via int4
// ---------------------------------------------------------------------------
__global__ void hist_kernel(const int* __restrict__ ei) {
    int i = blockIdx.x * 256 + threadIdx.x;       // int4 index
    if (i >= N_EDGES / 4) return;
    int4 d = ((const int4*)(ei + N_EDGES))[i];
    atomicAdd(&g_deg[d.x], 1);
    atomicAdd(&g_deg[d.y], 1);
    atomicAdd(&g_deg[d.z], 1);
    atomicAdd(&g_deg[d.w], 1);
}

// ---------------------------------------------------------------------------
// K2a: per-chunk totals (98 blocks x 256, 4 elems/thread)
// ---------------------------------------------------------------------------
__global__ void scanA_kernel() {
    __shared__ int sm[256];
    int base = blockIdx.x * SCAN_CHUNK;
    int s = 0;
    #pragma unroll
    for (int q = 0; q < 4; q++) {
        int idx = base + threadIdx.x + q * 256;
        if (idx < N_NODES) s += g_deg[idx];
    }
    sm[threadIdx.x] = s; __syncthreads();
    for (int st = 128; st > 0; st >>= 1) {
        if (threadIdx.x < st) sm[threadIdx.x] += sm[threadIdx.x + st];
        __syncthreads();
    }
    if (threadIdx.x == 0) g_csum[blockIdx.x] = sm[0];
}

// ---------------------------------------------------------------------------
// K2b: full scan — each block independently reduces its base from g_csum
// ---------------------------------------------------------------------------
__global__ void scanC_kernel() {
    __shared__ int warp_sums[32];
    __shared__ int sbase[128];
    int idx = blockIdx.x * SCAN_CHUNK + threadIdx.x;
    int d = (idx < N_NODES) ? g_deg[idx] : 0;

    if (threadIdx.x < 128) {
        int v = 0;
        if ((int)threadIdx.x < NCH && (int)threadIdx.x < (int)blockIdx.x)
            v = g_csum[threadIdx.x];
        sbase[threadIdx.x] = v;
    }
    __syncthreads();
    if (threadIdx.x < 64) sbase[threadIdx.x] += sbase[threadIdx.x + 64];
    __syncthreads();
    if (threadIdx.x < 32) {
        int v = sbase[threadIdx.x] + sbase[threadIdx.x + 32];
        #pragma unroll
        for (int o = 16; o > 0; o >>= 1) v += __shfl_down_sync(0xFFFFFFFFu, v, o);
        if (threadIdx.x == 0) sbase[0] = v;
    }

    int v = d;
    int lane = threadIdx.x & 31, wid = threadIdx.x >> 5;
    #pragma unroll
    for (int o = 1; o < 32; o <<= 1) {
        int t = __shfl_up_sync(0xFFFFFFFFu, v, o);
        if (lane >= o) v += t;
    }
    if (lane == 31) warp_sums[wid] = v;
    __syncthreads();
    if (wid == 0) {
        int s = warp_sums[lane];
        #pragma unroll
        for (int o = 1; o < 32; o <<= 1) {
            int t = __shfl_up_sync(0xFFFFFFFFu, s, o);
            if (lane >= o) s += t;
        }
        warp_sums[lane] = s;
    }
    __syncthreads();
    int incl = v + (wid > 0 ? warp_sums[wid - 1] : 0);
    int ex = sbase[0] + incl - d;
    if (idx < N_NODES) { g_off[idx] = ex; g_cur[idx] = ex; }
}

// ---------------------------------------------------------------------------
// K3: scatter packed (attr,src) — 4 edges/thread, 4 atomics in flight
// ---------------------------------------------------------------------------
__global__ void scatter_kernel(const int* __restrict__ ei, const int* __restrict__ ea) {
    int i = blockIdx.x * 256 + threadIdx.x;       // int4 index
    if (i >= N_EDGES / 4) return;
    int4 s = ((const int4*)ei)[i];
    int4 d = ((const int4*)(ei + N_EDGES))[i];
    int4 a = ((const int4*)ea)[i];
    int p0 = atomicAdd(&g_cur[d.x], 1);
    int p1 = atomicAdd(&g_cur[d.y], 1);
    int p2 = atomicAdd(&g_cur[d.z], 1);
    int p3 = atomicAdd(&g_cur[d.w], 1);
    g_es[p0] = (unsigned)s.x | ((unsigned)a.x << 28);
    g_es[p1] = (unsigned)s.y | ((unsigned)a.y << 28);
    g_es[p2] = (unsigned)s.z | ((unsigned)a.z << 28);
    g_es[p3] = (unsigned)s.w | ((unsigned)a.w << 28);
}

// ---------------------------------------------------------------------------
// K4: FUSED aggregate + GEMM1.
// Phase A (512 thr): 128 nodes/block, 4 lanes/node; register-accumulate
//   h = (1+eps)*x + sum relu(x[src]+emb[attr]); store tile to smem (k-major).
// Phase B (128 thr): t = h @ W1 + b1 (8x8 f32x2), write g_t, BN stats.
// ---------------------------------------------------------------------------
__global__ void __launch_bounds__(512, 1)
fused_kernel(const float* __restrict__ x, const float* __restrict__ emb,
             const float* __restrict__ eps,
             const float* __restrict__ W1, const float* __restrict__ b1) {
    extern __shared__ float sm[];
    float* sW   = sm + SM_W;
    float* sIn  = sm + SM_IN;
    float* s_emb = sm + SM_AUX;

    int t  = threadIdx.x;
    int r0 = blockIdx.x * 128;

    if (t < 256) s_emb[t] = emb[t];
    #pragma unroll
    for (int i = 0; i < 2; i++)
        ((float4*)sW)[t + i * 512] = ((const float4*)W1)[t + i * 512];
    __syncthreads();

    // ---- Phase A: gather-aggregate ----
    int nl = t >> 2, lane = t & 3;
    int node = r0 + nl;
    bool valid = node < N_NODES;

    float4 acc[4];
    {
        float s = 1.0f + __ldg(eps);
        const float4* xp = (const float4*)(x + (size_t)node * DIM + lane * 16);
        #pragma unroll
        for (int q = 0; q < 4; q++) {
            float4 v = valid ? __ldg(xp + q) : make_float4(0.f, 0.f, 0.f, 0.f);
            acc[q].x = v.x * s; acc[q].y = v.y * s;
            acc[q].z = v.z * s; acc[q].w = v.w * s;
        }
    }

    int off = 0, deg = 0;
    if (valid) { off = g_off[node]; deg = g_deg[node]; }

    int j = 0;
    for (; j + 2 <= deg; j += 2) {
        unsigned p0 = __ldg(g_es + off + j);
        unsigned p1 = __ldg(g_es + off + j + 1);
        const float4* x0 = (const float4*)(x + (size_t)(p0 & 0x0FFFFFFFu) * DIM + lane * 16);
        const float4* x1 = (const float4*)(x + (size_t)(p1 & 0x0FFFFFFFu) * DIM + lane * 16);
        const float4* e0 = (const float4*)(s_emb + (p0 >> 28) * DIM + lane * 16);
        const float4* e1 = (const float4*)(s_emb + (p1 >> 28) * DIM + lane * 16);
        #pragma unroll
        for (int q = 0; q < 4; q++) {
            float4 v0 = __ldg(x0 + q);
            float4 v1 = __ldg(x1 + q);
            float4 a0 = e0[q];
            float4 a1 = e1[q];
            acc[q].x += fmaxf(v0.x + a0.x, 0.0f) + fmaxf(v1.x + a1.x, 0.0f);
            acc[q].y += fmaxf(v0.y + a0.y, 0.0f) + fmaxf(v1.y + a1.y, 0.0f);
            acc[q].z += fmaxf(v0.z + a0.z, 0.0f) + fmaxf(v1.z + a1.z, 0.0f);
            acc[q].w += fmaxf(v0.w + a0.w, 0.0f) + fmaxf(v1.w + a1.w, 0.0f);
        }
    }
    if (j < deg) {
        unsigned p0 = __ldg(g_es + off + j);
        const float4* x0 = (const float4*)(x + (size_t)(p0 & 0x0FFFFFFFu) * DIM + lane * 16);
        const float4* e0 = (const float4*)(s_emb + (p0 >> 28) * DIM + lane * 16);
        #pragma unroll
        for (int q = 0; q < 4; q++) {
            float4 v0 = __ldg(x0 + q);
            float4 a0 = e0[q];
            acc[q].x += fmaxf(v0.x + a0.x, 0.0f);
            acc[q].y += fmaxf(v0.y + a0.y, 0.0f);
            acc[q].z += fmaxf(v0.z + a0.z, 0.0f);
            acc[q].w += fmaxf(v0.w + a0.w, 0.0f);
        }
    }

    // store transposed: sIn[k][node_local]
    #pragma unroll
    for (int q = 0; q < 4; q++) {
        int k0 = lane * 16 + q * 4;
        sIn[(k0 + 0) * IN_STRIDE + nl] = acc[q].x;
        sIn[(k0 + 1) * IN_STRIDE + nl] = acc[q].y;
        sIn[(k0 + 2) * IN_STRIDE + nl] = acc[q].z;
        sIn[(k0 + 3) * IN_STRIDE + nl] = acc[q].w;
    }
    __syncthreads();

    // ---- Phase B: GEMM (threads 0..127) ----
    int rg = t >> 3;   // 0..15 (valid for t<128)
    int cg = t & 7;
    float csum[8], csq[8];
    #pragma unroll
    for (int q = 0; q < 8; q++) { csum[q] = 0.0f; csq[q] = 0.0f; }

    if (t < 128) {
        unsigned long long acc2[8][4];
        #pragma unroll
        for (int i = 0; i < 8; i++)
            #pragma unroll
            for (int jp = 0; jp < 4; jp++) acc2[i][jp] = 0ull;

        #pragma unroll 2
        for (int k = 0; k < 64; k++) {
            float4 a0 = *(const float4*)(sIn + k * IN_STRIDE + rg * 8);
            float4 a1 = *(const float4*)(sIn + k * IN_STRIDE + rg * 8 + 4);
            float4 w0 = *(const float4*)(sW  + k * DIM + cg * 8);
            float4 w1 = *(const float4*)(sW  + k * DIM + cg * 8 + 4);
            unsigned long long w2[4];
            PACK2(w2[0], w0.x, w0.y);
            PACK2(w2[1], w0.z, w0.w);
            PACK2(w2[2], w1.x, w1.y);
            PACK2(w2[3], w1.z, w1.w);
            float av[8] = {a0.x, a0.y, a0.z, a0.w, a1.x, a1.y, a1.z, a1.w};
            #pragma unroll
            for (int i = 0; i < 8; i++) {
                unsigned long long ai;
                PACK2(ai, av[i], av[i]);
                #pragma unroll
                for (int jp = 0; jp < 4; jp++)
                    FMA2(acc2[i][jp], ai, w2[jp]);
            }
        }

        float bs[8];
        #pragma unroll
        for (int q = 0; q < 8; q++) bs[q] = b1[cg * 8 + q];

        #pragma unroll
        for (int i = 0; i < 8; i++) {
            int row = r0 + rg * 8 + i;
            if (row < N_NODES) {
                float v[8];
                #pragma unroll
                for (int jp = 0; jp < 4; jp++) {
                    float lo, hi;
                    UNPACK2(lo, hi, acc2[i][jp]);
                    v[2 * jp]     = lo + bs[2 * jp];
                    v[2 * jp + 1] = hi + bs[2 * jp + 1];
                }
                #pragma unroll
                for (int q = 0; q < 8; q++) { csum[q] += v[q]; csq[q] += v[q] * v[q]; }
                *(float4*)(g_t + (size_t)row * DIM + cg * 8)     = make_float4(v[0], v[1], v[2], v[3]);
                *(float4*)(g_t + (size_t)row * DIM + cg * 8 + 4) = make_float4(v[4], v[5], v[6], v[7]);
            }
        }
    }

    __syncthreads();
    float* red = sIn;   // reuse: 2048 floats
    if (t < 128) {
        #pragma unroll
        for (int q = 0; q < 8; q++) {
            red[rg * 64 + cg * 8 + q]        = csum[q];
            red[(16 + rg) * 64 + cg * 8 + q] = csq[q];
        }
    }
    __syncthreads();
    if (t < 64) {
        float s = 0.0f;
        #pragma unroll
        for (int g = 0; g < 16; g++) s += red[g * 64 + t];
        atomicAdd(&g_sum[t], s);
    } else if (t < 128) {
        int c = t - 64;
        float s = 0.0f;
        #pragma unroll
        for (int g = 0; g < 16; g++) s += red[(16 + g) * 64 + c];
        atomicAdd(&g_sq[c], s);
    }
}

// ---------------------------------------------------------------------------
// K5: out = relu(t*A + B) @ W2 + b2 (BN affine from g_sum/g_sq), 128 threads
// ---------------------------------------------------------------------------
__global__ void gemm2_kernel(const float* __restrict__ W, const float* __restrict__ bias,
                             const float* __restrict__ gamma, const float* __restrict__ beta,
                             float* __restrict__ out) {
    extern __shared__ float sm[];
    float* sW   = sm + SM_W;
    float* sIn  = sm + SM_IN;
    float* sAff = sm + SM_AUX;   // [2][64]

    int t  = threadIdx.x;        // 128 threads
    int r0 = blockIdx.x * 128;

    #pragma unroll
    for (int i = 0; i < 8; i++)
        ((float4*)sW)[t + i * 128] = ((const float4*)W)[t + i * 128];

    if (t < DIM) {
        const float inv = 1.0f / (float)N_NODES;
        float mu  = g_sum[t] * inv;
        float var = g_sq[t] * inv - mu * mu;
        float a   = gamma[t] * rsqrtf(var + 1e-5f);
        sAff[t]       = a;
        sAff[DIM + t] = fmaf(-mu, a, beta[t]);
    }
    __syncthreads();

    {
        int row = r0 + t;
        bool valid = row < N_NODES;
        const float4* rp = (const float4*)(g_t + (size_t)row * DIM);
        #pragma unroll
        for (int q = 0; q < 16; q++) {
            float4 v = valid ? __ldg(rp + q) : make_float4(0.f, 0.f, 0.f, 0.f);
            int k0 = q * 4;
            v.x = fmaxf(fmaf(v.x, sAff[k0 + 0], sAff[DIM + k0 + 0]), 0.0f);
            v.y = fmaxf(fmaf(v.y, sAff[k0 + 1], sAff[DIM + k0 + 1]), 0.0f);
            v.z = fmaxf(fmaf(v.z, sAff[k0 + 2], sAff[DIM + k0 + 2]), 0.0f);
            v.w = fmaxf(fmaf(v.w, sAff[k0 + 3], sAff[DIM + k0 + 3]), 0.0f);
            sIn[(k0 + 0) * IN_STRIDE + t] = v.x;
            sIn[(k0 + 1) * IN_STRIDE + t] = v.y;
            sIn[(k0 + 2) * IN_STRIDE + t] = v.z;
            sIn[(k0 + 3) * IN_STRIDE + t] = v.w;
        }
    }
    __syncthreads();

    int rg = t >> 3;
    int cg = t & 7;

    unsigned long long acc2[8][4];
    #pragma unroll
    for (int i = 0; i < 8; i++)
        #pragma unroll
        for (int jp = 0; jp < 4; jp++) acc2[i][jp] = 0ull;

    #pragma unroll 2
    for (int k = 0; k < 64; k++) {
        float4 a0 = *(const float4*)(sIn + k * IN_STRIDE + rg * 8);
        float4 a1 = *(const float4*)(sIn + k * IN_STRIDE + rg * 8 + 4);
        float4 w0 = *(const float4*)(sW  + k * DIM + cg * 8);
        float4 w1 = *(const float4*)(sW  + k * DIM + cg * 8 + 4);
        unsigned long long w2[4];
        PACK2(w2[0], w0.x, w0.y);
        PACK2(w2[1], w0.z, w0.w);
        PACK2(w2[2], w1.x, w1.y);
        PACK2(w2[3], w1.z, w1.w);
        float av[8] = {a0.x, a0.y, a0.z, a0.w, a1.x, a1.y, a1.z, a1.w};
        #pragma unroll
        for (int i = 0; i < 8; i++) {
            unsigned long long ai;
            PACK2(ai, av[i], av[i]);
            #pragma unroll
            for (int jp = 0; jp < 4; jp++)
                FMA2(acc2[i][jp], ai, w2[jp]);
        }
    }

    float bs[8];
    #pragma unroll
    for (int q = 0; q < 8; q++) bs[q] = bias[cg * 8 + q];

    #pragma unroll
    for (int i = 0; i < 8; i++) {
        int row = r0 + rg * 8 + i;
        if (row < N_NODES) {
            float v[8];
            #pragma unroll
            for (int jp = 0; jp < 4; jp++) {
                float lo, hi;
                UNPACK2(lo, hi, acc2[i][jp]);
                v[2 * jp]     = lo + bs[2 * jp];
                v[2 * jp + 1] = hi + bs[2 * jp + 1];
            }
            *(float4*)(out + (size_t)row * DIM + cg * 8)     = make_float4(v[0], v[1], v[2], v[3]);
            *(float4*)(out + (size_t)row * DIM + cg * 8 + 4) = make_float4(v[4], v[5], v[6], v[7]);
        }
    }
}

// ---------------------------------------------------------------------------
extern "C" void kernel_launch(void* const* d_in, const int* in_sizes, int n_in,
                              void* d_out, int out_size) {
    const float* x     = (const float*)d_in[0];
    const float* emb   = (const float*)d_in[1];
    const float* eps   = (const float*)d_in[2];
    const float* W1    = (const float*)d_in[3];
    const float* b1    = (const float*)d_in[4];
    const float* gamma = (const float*)d_in[5];
    const float* beta  = (const float*)d_in[6];
    const float* W2    = (const float*)d_in[7];
    const float* b2    = (const float*)d_in[8];
    const int*   ei    = (const int*)d_in[9];
    const int*   ea    = (const int*)d_in[10];
    float*       out   = (float*)d_out;

    const int smem_bytes = SMEM_FLOATS * 4;   // ~51.2KB: opt in
    cudaFuncSetAttribute(fused_kernel, cudaFuncAttributeMaxDynamicSharedMemorySize, smem_bytes);
    cudaFuncSetAttribute(gemm2_kernel, cudaFuncAttributeMaxDynamicSharedMemorySize, smem_bytes);

    const int e4blocks = (N_EDGES / 4 + 255) / 256;       // 1563
    zero_kernel<<<(N_NODES + 255) / 256, 256>>>();
    hist_kernel<<<e4blocks, 256>>>(ei);
    scanA_kernel<<<NCH, 256>>>();
    scanC_kernel<<<NCH, SCAN_CHUNK>>>();
    scatter_kernel<<<e4blocks, 256>>>(ei, ea);
    const int gblocks = (N_NODES + 127) / 128;            // 782
    fused_kernel<<<gblocks, 512, smem_bytes>>>(x, emb, eps, W1, b1);
    gemm2_kernel<<<gblocks, 128, smem_bytes>>>(W2, b2, gamma, beta, out);
}

// round 6
// speedup vs baseline: 1.4392x; 1.4392x over previous
#include <cuda_runtime.h>
#include <cuda_fp16.h>

#define N_NODES 100000
#define N_EDGES 1600000
#define DIM 64
#define SCAN_CHUNK 1024
#define NCH ((N_NODES + SCAN_CHUNK - 1) / SCAN_CHUNK)   // 98

// scratch (allocation-free: device globals)
__device__ float  g_h[(size_t)N_NODES * DIM];   // (1+eps)*x + agg
__device__ float  g_t[(size_t)N_NODES * DIM];   // h@W1 + b1
__device__ __half g_x16[(size_t)N_NODES * DIM]; // fp16 copy of x (gather path)
__device__ float  g_sum[DIM];
__device__ float  g_sq[DIM];
__device__ int    g_deg[N_NODES];
__device__ int    g_off[N_NODES];
__device__ int    g_cur[N_NODES];
__device__ int    g_csum[NCH];
__device__ unsigned g_es[N_EDGES];              // (attr<<28) | src

#define PACK2(d, lo, hi)  asm("mov.b64 %0, {%1, %2};" : "=l"(d) : "f"(lo), "f"(hi))
#define UNPACK2(lo, hi, s) asm("mov.b64 {%0, %1}, %2;" : "=f"(lo), "=f"(hi) : "l"(s))
#define FMA2(acc, a, b)   asm("fma.rn.f32x2 %0, %1, %2, %0;" : "+l"(acc) : "l"(a), "l"(b))

// ---------------------------------------------------------------------------
// K0: prep — convert x -> fp16 (8 floats/thread), zero counters + BN accums
// ---------------------------------------------------------------------------
__global__ void prep_kernel(const float* __restrict__ x) {
    int i = blockIdx.x * 256 + threadIdx.x;
    if (i < N_NODES * DIM / 8) {
        float4 a = __ldg((const float4*)x + 2 * i);
        float4 b = __ldg((const float4*)x + 2 * i + 1);
        __half2 h0 = __floats2half2_rn(a.x, a.y);
        __half2 h1 = __floats2half2_rn(a.z, a.w);
        __half2 h2 = __floats2half2_rn(b.x, b.y);
        __half2 h3 = __floats2half2_rn(b.z, b.w);
        uint4 p;
        p.x = *(unsigned*)&h0; p.y = *(unsigned*)&h1;
        p.z = *(unsigned*)&h2; p.w = *(unsigned*)&h3;
        ((uint4*)g_x16)[i] = p;
    }
    if (i < N_NODES) g_deg[i] = 0;
    if (i < DIM) { g_sum[i] = 0.0f; g_sq[i] = 0.0f; }
}

// ---------------------------------------------------------------------------
// K1: histogram of dst — 4 edges/thread via int4
// ---------------------------------------------------------------------------
__global__ void hist_kernel(const int* __restrict__ ei) {
    int i = blockIdx.x * 256 + threadIdx.x;       // int4 index
    if (i >= N_EDGES / 4) return;
    int4 d = ((const int4*)(ei + N_EDGES))[i];
    atomicAdd(&g_deg[d.x], 1);
    atomicAdd(&g_deg[d.y], 1);
    atomicAdd(&g_deg[d.z], 1);
    atomicAdd(&g_deg[d.w], 1);
}

// ---------------------------------------------------------------------------
// K2a: per-chunk totals (98 blocks x 256, 4 elems/thread)
// ---------------------------------------------------------------------------
__global__ void scanA_kernel() {
    __shared__ int sm[256];
    int base = blockIdx.x * SCAN_CHUNK;
    int s = 0;
    #pragma unroll
    for (int q = 0; q < 4; q++) {
        int idx = base + threadIdx.x + q * 256;
        if (idx < N_NODES) s += g_deg[idx];
    }
    sm[threadIdx.x] = s; __syncthreads();
    for (int st = 128; st > 0; st >>= 1) {
        if (threadIdx.x < st) sm[threadIdx.x] += sm[threadIdx.x + st];
        __syncthreads();
    }
    if (threadIdx.x == 0) g_csum[blockIdx.x] = sm[0];
}

// ---------------------------------------------------------------------------
// K2b: full scan — each block independently reduces its base from g_csum
// ---------------------------------------------------------------------------
__global__ void scanC_kernel() {
    __shared__ int warp_sums[32];
    __shared__ int sbase[128];
    int idx = blockIdx.x * SCAN_CHUNK + threadIdx.x;
    int d = (idx < N_NODES) ? g_deg[idx] : 0;

    if (threadIdx.x < 128) {
        int v = 0;
        if ((int)threadIdx.x < NCH && (int)threadIdx.x < (int)blockIdx.x)
            v = g_csum[threadIdx.x];
        sbase[threadIdx.x] = v;
    }
    __syncthreads();
    if (threadIdx.x < 64) sbase[threadIdx.x] += sbase[threadIdx.x + 64];
    __syncthreads();
    if (threadIdx.x < 32) {
        int v = sbase[threadIdx.x] + sbase[threadIdx.x + 32];
        #pragma unroll
        for (int o = 16; o > 0; o >>= 1) v += __shfl_down_sync(0xFFFFFFFFu, v, o);
        if (threadIdx.x == 0) sbase[0] = v;
    }

    int v = d;
    int lane = threadIdx.x & 31, wid = threadIdx.x >> 5;
    #pragma unroll
    for (int o = 1; o < 32; o <<= 1) {
        int t = __shfl_up_sync(0xFFFFFFFFu, v, o);
        if (lane >= o) v += t;
    }
    if (lane == 31) warp_sums[wid] = v;
    __syncthreads();
    if (wid == 0) {
        int s = warp_sums[lane];
        #pragma unroll
        for (int o = 1; o < 32; o <<= 1) {
            int t = __shfl_up_sync(0xFFFFFFFFu, s, o);
            if (lane >= o) s += t;
        }
        warp_sums[lane] = s;
    }
    __syncthreads();
    int incl = v + (wid > 0 ? warp_sums[wid - 1] : 0);
    int ex = sbase[0] + incl - d;
    if (idx < N_NODES) { g_off[idx] = ex; g_cur[idx] = ex; }
}

// ---------------------------------------------------------------------------
// K3: scatter packed (attr,src) — 4 edges/thread, 4 atomics in flight
// ---------------------------------------------------------------------------
__global__ void scatter_kernel(const int* __restrict__ ei, const int* __restrict__ ea) {
    int i = blockIdx.x * 256 + threadIdx.x;       // int4 index
    if (i >= N_EDGES / 4) return;
    int4 s = ((const int4*)ei)[i];
    int4 d = ((const int4*)(ei + N_EDGES))[i];
    int4 a = ((const int4*)ea)[i];
    int p0 = atomicAdd(&g_cur[d.x], 1);
    int p1 = atomicAdd(&g_cur[d.y], 1);
    int p2 = atomicAdd(&g_cur[d.z], 1);
    int p3 = atomicAdd(&g_cur[d.w], 1);
    g_es[p0] = (unsigned)s.x | ((unsigned)a.x << 28);
    g_es[p1] = (unsigned)s.y | ((unsigned)a.y << 28);
    g_es[p2] = (unsigned)s.z | ((unsigned)a.z << 28);
    g_es[p3] = (unsigned)s.w | ((unsigned)a.w << 28);
}

// ---------------------------------------------------------------------------
// K4: aggregate — per node, register-accumulate relu(x16[src]+emb[attr]),
//     self term in exact fp32; 16 lanes per node (4 floats each), MLP=4.
// ---------------------------------------------------------------------------
__global__ void agg_kernel(const float* __restrict__ x, const float* __restrict__ emb,
                           const float* __restrict__ eps) {
    __shared__ float s_emb[4 * DIM];
    s_emb[threadIdx.x] = emb[threadIdx.x];   // 256 threads == 256 floats
    __syncthreads();

    unsigned gt = blockIdx.x * 256u + threadIdx.x;
    unsigned n = gt >> 4;
    unsigned lane = gt & 15u;
    if (n >= N_NODES) return;

    int off = g_off[n];
    int deg = g_deg[n];
    float s = 1.0f + __ldg(eps);

    float4 acc = *(const float4*)(x + (size_t)n * DIM + lane * 4);
    acc.x *= s; acc.y *= s; acc.z *= s; acc.w *= s;

    float4 em_cache = *(const float4*)(s_emb + lane * 4);  // attr 0 row (warm)
    (void)em_cache;

    const uint2* xb = (const uint2*)g_x16;   // 16 uint2 per 64-half row

    int j = 0;
    for (; j + 4 <= deg; j += 4) {
        unsigned p0 = __ldg(g_es + off + j);
        unsigned p1 = __ldg(g_es + off + j + 1);
        unsigned p2 = __ldg(g_es + off + j + 2);
        unsigned p3 = __ldg(g_es + off + j + 3);
        uint2 r0 = __ldg(xb + (size_t)(p0 & 0x0FFFFFFFu) * 16 + lane);
        uint2 r1 = __ldg(xb + (size_t)(p1 & 0x0FFFFFFFu) * 16 + lane);
        uint2 r2 = __ldg(xb + (size_t)(p2 & 0x0FFFFFFFu) * 16 + lane);
        uint2 r3 = __ldg(xb + (size_t)(p3 & 0x0FFFFFFFu) * 16 + lane);
        float4 e0 = *(const float4*)(s_emb + (p0 >> 28) * DIM + lane * 4);
        float4 e1 = *(const float4*)(s_emb + (p1 >> 28) * DIM + lane * 4);
        float4 e2 = *(const float4*)(s_emb + (p2 >> 28) * DIM + lane * 4);
        float4 e3 = *(const float4*)(s_emb + (p3 >> 28) * DIM + lane * 4);
        float2 f0a = __half22float2(*(__half2*)&r0.x), f0b = __half22float2(*(__half2*)&r0.y);
        float2 f1a = __half22float2(*(__half2*)&r1.x), f1b = __half22float2(*(__half2*)&r1.y);
        float2 f2a = __half22float2(*(__half2*)&r2.x), f2b = __half22float2(*(__half2*)&r2.y);
        float2 f3a = __half22float2(*(__half2*)&r3.x), f3b = __half22float2(*(__half2*)&r3.y);
        acc.x += fmaxf(f0a.x + e0.x, 0.0f) + fmaxf(f1a.x + e1.x, 0.0f)
               + fmaxf(f2a.x + e2.x, 0.0f) + fmaxf(f3a.x + e3.x, 0.0f);
        acc.y += fmaxf(f0a.y + e0.y, 0.0f) + fmaxf(f1a.y + e1.y, 0.0f)
               + fmaxf(f2a.y + e2.y, 0.0f) + fmaxf(f3a.y + e3.y, 0.0f);
        acc.z += fmaxf(f0b.x + e0.z, 0.0f) + fmaxf(f1b.x + e1.z, 0.0f)
               + fmaxf(f2b.x + e2.z, 0.0f) + fmaxf(f3b.x + e3.z, 0.0f);
        acc.w += fmaxf(f0b.y + e0.w, 0.0f) + fmaxf(f1b.y + e1.w, 0.0f)
               + fmaxf(f2b.y + e2.w, 0.0f) + fmaxf(f3b.y + e3.w, 0.0f);
    }
    for (; j < deg; j++) {
        unsigned p0 = __ldg(g_es + off + j);
        uint2 r0 = __ldg(xb + (size_t)(p0 & 0x0FFFFFFFu) * 16 + lane);
        float4 e0 = *(const float4*)(s_emb + (p0 >> 28) * DIM + lane * 4);
        float2 f0a = __half22float2(*(__half2*)&r0.x), f0b = __half22float2(*(__half2*)&r0.y);
        acc.x += fmaxf(f0a.x + e0.x, 0.0f);
        acc.y += fmaxf(f0a.y + e0.y, 0.0f);
        acc.z += fmaxf(f0b.x + e0.z, 0.0f);
        acc.w += fmaxf(f0b.y + e0.w, 0.0f);
    }
    *(float4*)(g_h + (size_t)n * DIM + lane * 4) = acc;
}

// ---------------------------------------------------------------------------
// K5/K6: 128x64 tile GEMM, 8x8 per thread, fma.rn.f32x2 inner loop.
// MODE 0: t = g_h @ W1 + b1, write g_t, accumulate column sum/sumsq
// MODE 1: out = relu(t*A + B) @ W2 + b2, BN affine computed from g_sum/g_sq
// ---------------------------------------------------------------------------
#define TILE_R    128
#define IN_STRIDE 132
#define SMEM_FLOATS (DIM * DIM + DIM * IN_STRIDE + 2 * DIM)   // 12672

template <int MODE>
__global__ void gemm_kernel(const float* __restrict__ W, const float* __restrict__ bias,
                            const float* __restrict__ gamma, const float* __restrict__ beta,
                            float* __restrict__ out_ext) {
    extern __shared__ float sm[];
    float* sW   = sm;                               // [64][64]
    float* sIn  = sm + DIM * DIM;                   // [64][IN_STRIDE] k-major
    float* sAff = sm + DIM * DIM + DIM * IN_STRIDE; // [2][64]

    const float* in  = (MODE == 0) ? g_h : g_t;
    float*       out = (MODE == 0) ? g_t : out_ext;

    int t  = threadIdx.x;            // 128 threads
    int r0 = blockIdx.x * TILE_R;

    #pragma unroll
    for (int i = 0; i < 8; i++)
        ((float4*)sW)[t + i * 128] = ((const float4*)W)[t + i * 128];

    if (MODE == 1) {
        if (t < DIM) {
            const float inv = 1.0f / (float)N_NODES;
            float mu  = g_sum[t] * inv;
            float var = g_sq[t] * inv - mu * mu;
            float a   = gamma[t] * rsqrtf(var + 1e-5f);
            sAff[t]       = a;
            sAff[DIM + t] = fmaf(-mu, a, beta[t]);
        }
        __syncthreads();
    }

    {
        int row = r0 + t;
        bool valid = row < N_NODES;
        const float4* rp = (const float4*)(in + (size_t)row * DIM);
        #pragma unroll
        for (int q = 0; q < 16; q++) {
            float4 v = valid ? __ldg(rp + q) : make_float4(0.f, 0.f, 0.f, 0.f);
            int k0 = q * 4;
            if (MODE == 1) {
                v.x = fmaxf(fmaf(v.x, sAff[k0 + 0], sAff[DIM + k0 + 0]), 0.0f);
                v.y = fmaxf(fmaf(v.y, sAff[k0 + 1], sAff[DIM + k0 + 1]), 0.0f);
                v.z = fmaxf(fmaf(v.z, sAff[k0 + 2], sAff[DIM + k0 + 2]), 0.0f);
                v.w = fmaxf(fmaf(v.w, sAff[k0 + 3], sAff[DIM + k0 + 3]), 0.0f);
            }
            sIn[(k0 + 0) * IN_STRIDE + t] = v.x;
            sIn[(k0 + 1) * IN_STRIDE + t] = v.y;
            sIn[(k0 + 2) * IN_STRIDE + t] = v.z;
            sIn[(k0 + 3) * IN_STRIDE + t] = v.w;
        }
    }
    __syncthreads();

    int rg = t >> 3;  // 0..15
    int cg = t & 7;   // 0..7

    unsigned long long acc2[8][4];
    #pragma unroll
    for (int i = 0; i < 8; i++)
        #pragma unroll
        for (int jp = 0; jp < 4; jp++) acc2[i][jp] = 0ull;

    #pragma unroll 2
    for (int k = 0; k < 64; k++) {
        float4 a0 = *(const float4*)(sIn + k * IN_STRIDE + rg * 8);
        float4 a1 = *(const float4*)(sIn + k * IN_STRIDE + rg * 8 + 4);
        float4 w0 = *(const float4*)(sW  + k * DIM + cg * 8);
        float4 w1 = *(const float4*)(sW  + k * DIM + cg * 8 + 4);
        unsigned long long w2[4];
        PACK2(w2[0], w0.x, w0.y);
        PACK2(w2[1], w0.z, w0.w);
        PACK2(w2[2], w1.x, w1.y);
        PACK2(w2[3], w1.z, w1.w);
        float av[8] = {a0.x, a0.y, a0.z, a0.w, a1.x, a1.y, a1.z, a1.w};
        #pragma unroll
        for (int i = 0; i < 8; i++) {
            unsigned long long ai;
            PACK2(ai, av[i], av[i]);
            #pragma unroll
            for (int jp = 0; jp < 4; jp++)
                FMA2(acc2[i][jp], ai, w2[jp]);
        }
    }

    float bs[8];
    #pragma unroll
    for (int j = 0; j < 8; j++) bs[j] = bias[cg * 8 + j];

    float csum[8], csq[8];
    #pragma unroll
    for (int j = 0; j < 8; j++) { csum[j] = 0.0f; csq[j] = 0.0f; }

    #pragma unroll
    for (int i = 0; i < 8; i++) {
        int row = r0 + rg * 8 + i;
        if (row < N_NODES) {
            float v[8];
            #pragma unroll
            for (int jp = 0; jp < 4; jp++) {
                float lo, hi;
                UNPACK2(lo, hi, acc2[i][jp]);
                v[2 * jp]     = lo + bs[2 * jp];
                v[2 * jp + 1] = hi + bs[2 * jp + 1];
            }
            if (MODE == 0) {
                #pragma unroll
                for (int j = 0; j < 8; j++) { csum[j] += v[j]; csq[j] += v[j] * v[j]; }
            }
            *(float4*)(out + (size_t)row * DIM + cg * 8)     = make_float4(v[0], v[1], v[2], v[3]);
            *(float4*)(out + (size_t)row * DIM + cg * 8 + 4) = make_float4(v[4], v[5], v[6], v[7]);
        }
    }

    if (MODE == 0) {
        __syncthreads();
        float* red = sIn;
        #pragma unroll
        for (int j = 0; j < 8; j++) {
            red[rg * 64 + cg * 8 + j]        = csum[j];
            red[(16 + rg) * 64 + cg * 8 + j] = csq[j];
        }
        __syncthreads();
        if (t < 64) {
            float s = 0.0f;
            #pragma unroll
            for (int g = 0; g < 16; g++) s += red[g * 64 + t];
            atomicAdd(&g_sum[t], s);
        } else {
            int c = t - 64;
            float s = 0.0f;
            #pragma unroll
            for (int g = 0; g < 16; g++) s += red[(16 + g) * 64 + c];
            atomicAdd(&g_sq[c], s);
        }
    }
}

// ---------------------------------------------------------------------------
extern "C" void kernel_launch(void* const* d_in, const int* in_sizes, int n_in,
                              void* d_out, int out_size) {
    const float* x     = (const float*)d_in[0];
    const float* emb   = (const float*)d_in[1];
    const float* eps   = (const float*)d_in[2];
    const float* W1    = (const float*)d_in[3];
    const float* b1    = (const float*)d_in[4];
    const float* gamma = (const float*)d_in[5];
    const float* beta  = (const float*)d_in[6];
    const float* W2    = (const float*)d_in[7];
    const float* b2    = (const float*)d_in[8];
    const int*   ei    = (const int*)d_in[9];
    const int*   ea    = (const int*)d_in[10];
    float*       out   = (float*)d_out;

    const int smem_bytes = SMEM_FLOATS * 4;  // 50688 > 48K: opt in
    cudaFuncSetAttribute(gemm_kernel<0>, cudaFuncAttributeMaxDynamicSharedMemorySize, smem_bytes);
    cudaFuncSetAttribute(gemm_kernel<1>, cudaFuncAttributeMaxDynamicSharedMemorySize, smem_bytes);

    const int e4blocks = (N_EDGES / 4 + 255) / 256;       // 1563
    prep_kernel<<<(N_NODES * DIM / 8 + 255) / 256, 256>>>(x);
    hist_kernel<<<e4blocks, 256>>>(ei);
    scanA_kernel<<<NCH, 256>>>();
    scanC_kernel<<<NCH, SCAN_CHUNK>>>();
    scatter_kernel<<<e4blocks, 256>>>(ei, ea);
    agg_kernel<<<(N_NODES * 16 + 255) / 256, 256>>>(x, emb, eps);
    const int gblocks = (N_NODES + TILE_R - 1) / TILE_R;  // 782
    gemm_kernel<0><<<gblocks, 128, smem_bytes>>>(W1, b1, nullptr, nullptr, nullptr);
    gemm_kernel<1><<<gblocks, 128, smem_bytes>>>(W2, b2, gamma, beta, out);
}